// round 11
// baseline (speedup 1.0000x reference)
#include <cuda_runtime.h>
#include <cuda_bf16.h>
#include <math.h>
#include <stdint.h>

// ---------------- problem constants ----------------
#define BT      2048
#define BSEQ    4
#define TSEQ    512
#define HDIM    1024
#define VOCAB   32000
#define IGNORE_INDEX (-100)
#define BETA    0.1f
#define INV512  0.001953125f

// GEMM tiling
#define TILE_M   128
#define TILE_N   128
#define KSTAGE   32                  // k elems per stage
#define NSTAGES  (HDIM / KSTAGE)     // 32
#define NTILES_M (BT / TILE_M)       // 16
#define NTILES_N (VOCAB / TILE_N)    // 250
#define NTHREADS 512

// smem: 4 stages x (Ah 8K + Bh 8K + A8 8K + B8 8K) = 4 x 32KB
// bf16 tiles: 128 rows x 64B (k32 bf16). fp8 tiles: 128 rows x 64B
//   (bytes [0,32) = hi-fp8 of k-stage, [32,64) = lo-fp8).
#define T8K       8192u
#define STAGE_B   (4u * T8K)                        // 32768
#define SM_AH(b)  ((b) * STAGE_B + 0u)
#define SM_BH(b)  ((b) * STAGE_B + T8K)
#define SM_A8(b)  ((b) * STAGE_B + 2u * T8K)
#define SM_B8(b)  ((b) * STAGE_B + 3u * T8K)
#define SMEM_DYN  (4u * STAGE_B + 1024u)

// ---------------- device scratch (static) ----------------
__device__ __nv_bfloat16 g_whi[2ULL * VOCAB * HDIM];
__device__ unsigned char g_wh8[2ULL * VOCAB * HDIM];
__device__ unsigned char g_wl8[2ULL * VOCAB * HDIM];
__device__ __nv_bfloat16 g_xhi[2ULL * BT * HDIM];
__device__ unsigned char g_xh8[2ULL * BT * HDIM];
__device__ unsigned char g_xl8[2ULL * BT * HDIM];
__device__ float2 g_partials[2][(size_t)NTILES_N * BT];
__device__ float  g_tgt[2][BT];
__device__ float  g_seq[2][BSEQ];

// ---------------- helpers ----------------
__device__ __forceinline__ uint32_t smem_u32(const void* p) {
    uint32_t a;
    asm("{ .reg .u64 t; cvta.to.shared.u64 t, %1; cvt.u32.u64 %0, t; }" : "=r"(a) : "l"(p));
    return a;
}
// SW64 swizzle for 64B rows
__device__ __forceinline__ uint32_t swz64(uint32_t off) {
    return off ^ ((off >> 3) & 0x30u);
}
__device__ __forceinline__ void ldmatrix_x4(uint32_t* r, uint32_t addr) {
    asm volatile("ldmatrix.sync.aligned.m8n8.x4.shared.b16 {%0,%1,%2,%3}, [%4];"
                 : "=r"(r[0]), "=r"(r[1]), "=r"(r[2]), "=r"(r[3]) : "r"(addr));
}
__device__ __forceinline__ void mma16816(float* d, const uint32_t* a,
                                         uint32_t b0, uint32_t b1) {
    asm volatile("mma.sync.aligned.m16n8k16.row.col.f32.bf16.bf16.f32 "
                 "{%0,%1,%2,%3}, {%4,%5,%6,%7}, {%8,%9}, {%0,%1,%2,%3};"
                 : "+f"(d[0]), "+f"(d[1]), "+f"(d[2]), "+f"(d[3])
                 : "r"(a[0]), "r"(a[1]), "r"(a[2]), "r"(a[3]), "r"(b0), "r"(b1));
}
__device__ __forceinline__ void mma_fp8(float* d, const uint32_t* a,
                                        uint32_t b0, uint32_t b1) {
    asm volatile("mma.sync.aligned.m16n8k32.row.col.f32.e4m3.e4m3.f32 "
                 "{%0,%1,%2,%3}, {%4,%5,%6,%7}, {%8,%9}, {%0,%1,%2,%3};"
                 : "+f"(d[0]), "+f"(d[1]), "+f"(d[2]), "+f"(d[3])
                 : "r"(a[0]), "r"(a[1]), "r"(a[2]), "r"(a[3]), "r"(b0), "r"(b1));
}
__device__ __forceinline__ unsigned short cvt_e4m3x2(float hi, float lo) {
    unsigned short r;
    asm("cvt.rn.satfinite.e4m3x2.f32 %0, %1, %2;" : "=h"(r) : "f"(hi), "f"(lo));
    return r;   // (fp8(hi)<<8) | fp8(lo)
}

// ---------------- dtype detection ----------------
__device__ __forceinline__ bool target_is_i64(const void* t) {
    const int* w = (const int*)t;
    bool is64 = true;
    #pragma unroll
    for (int i = 0; i < 32; i++)
        if (w[2 * i + 1] != 0) is64 = false;
    return is64;
}
__device__ __forceinline__ long long load_tgt(const void* t, int i, bool is64) {
    return is64 ? ((const long long*)t)[i] : (long long)((const int*)t)[i];
}

// =================================================================
// Kernel 0: fp32 -> bf16 hi, e4m3(value), e4m3(residual*512)
// =================================================================
__global__ __launch_bounds__(256)
void split3_kernel(const float* __restrict__ src, __nv_bfloat16* __restrict__ hi,
                   unsigned char* __restrict__ h8, unsigned char* __restrict__ l8,
                   long long n4)
{
    long long stride = (long long)gridDim.x * blockDim.x;
    const float4* s4 = (const float4*)src;
    uint2* hv = (uint2*)hi;
    uint32_t* h8v = (uint32_t*)h8;
    uint32_t* l8v = (uint32_t*)l8;
    for (long long i = (long long)blockIdx.x * blockDim.x + threadIdx.x; i < n4; i += stride) {
        float4 v = s4[i];
        float f[4] = {v.x, v.y, v.z, v.w};
        unsigned short hb[4];
        float r[4];
        #pragma unroll
        for (int j = 0; j < 4; j++) {
            __nv_bfloat16 h = __float2bfloat16_rn(f[j]);
            hb[j] = __bfloat16_as_ushort(h);
            r[j]  = (f[j] - __bfloat162float(h)) * 512.0f;
        }
        uint2 ho;
        ho.x = (uint32_t)hb[0] | ((uint32_t)hb[1] << 16);
        ho.y = (uint32_t)hb[2] | ((uint32_t)hb[3] << 16);
        hv[i] = ho;
        uint32_t hp = (uint32_t)cvt_e4m3x2(f[1], f[0])
                    | ((uint32_t)cvt_e4m3x2(f[3], f[2]) << 16);
        uint32_t lp = (uint32_t)cvt_e4m3x2(r[1], r[0])
                    | ((uint32_t)cvt_e4m3x2(r[3], r[2]) << 16);
        h8v[i] = hp;
        l8v[i] = lp;
    }
}

// =================================================================
// Kernel 1: bf16 main + fp8 correction GEMM, fused online softmax
//   grid (16, 250, 2), block 512 (16 warps: 4m x 4n), warp tile 32x32
// =================================================================
__device__ __forceinline__ void cp_bf16_tile(uint32_t dst, const __nv_bfloat16* src,
                                             int tid)
{
    // 128 rows x 64B; 512 chunks of 16B; 512 threads -> 1 each
    int r = tid >> 2;
    int c = tid & 3;
    uint32_t off = (uint32_t)r * 64u + (uint32_t)c * 16u;
    const char* g = (const char*)src + (size_t)r * (HDIM * 2) + c * 16;
    asm volatile("cp.async.cg.shared.global [%0], [%1], 16;"
                 :: "r"(dst + swz64(off)), "l"(g) : "memory");
}
__device__ __forceinline__ void cp_fp8_tile(uint32_t dst, const unsigned char* srcHi,
                                            const unsigned char* srcLo, int tid)
{
    // 128 rows x 64B (hi 32B + lo 32B); 512 chunks; 512 threads -> 1 each
    int r = tid >> 2;
    int c = tid & 3;
    int half = c >> 1;
    int cc = c & 1;
    uint32_t off = (uint32_t)r * 64u + (uint32_t)half * 32u + (uint32_t)cc * 16u;
    const unsigned char* s = half ? srcLo : srcHi;
    const char* g = (const char*)s + (size_t)r * HDIM + cc * 16;
    asm volatile("cp.async.cg.shared.global [%0], [%1], 16;"
                 :: "r"(dst + swz64(off)), "l"(g) : "memory");
}

__global__ __launch_bounds__(NTHREADS, 1)
void lse_mma_kernel(const float* __restrict__ b0v, const float* __restrict__ b1v)
{
    extern __shared__ char dsm[];
    __shared__ float bias_sm[TILE_N];
    __shared__ float redM[4][TILE_M];
    __shared__ float redS[4][TILE_M];

    const int tid  = threadIdx.x;
    const int wid  = tid >> 5;
    const int lane = tid & 31;
    const int warp_m = wid & 3;        // 0..3 (32 rows each)
    const int warp_n = wid >> 2;       // 0..3 (32 cols each)

    uint32_t raw  = smem_u32(dsm);
    uint32_t base = (raw + 1023u) & ~1023u;

    const int m0   = blockIdx.x * TILE_M;
    const int n0   = blockIdx.y * TILE_N;
    const int pass = blockIdx.z;
    const float* BV = pass ? b1v : b0v;

    const __nv_bfloat16*  Ah  = g_xhi + ((size_t)pass * BT + m0) * HDIM;
    const unsigned char*  Ah8 = g_xh8 + ((size_t)pass * BT + m0) * HDIM;
    const unsigned char*  Al8 = g_xl8 + ((size_t)pass * BT + m0) * HDIM;
    const __nv_bfloat16*  Bh  = g_whi + ((size_t)pass * VOCAB + n0) * HDIM;
    const unsigned char*  Bh8 = g_wh8 + ((size_t)pass * VOCAB + n0) * HDIM;
    const unsigned char*  Bl8 = g_wl8 + ((size_t)pass * VOCAB + n0) * HDIM;

    if (tid < TILE_N) bias_sm[tid] = BV[n0 + tid];

    // ---- per-lane ldmatrix offsets (tile-relative, swizzled) ----
    uint32_t aoffM[2][2], boffM[2][2];     // bf16: [ks][mi] / [ks][np]
    uint32_t aoff8[2][2], boff8[2][2];     // fp8:  [half][mi] / [half][np]
    #pragma unroll
    for (int ks = 0; ks < 2; ks++) {
        #pragma unroll
        for (int mi = 0; mi < 2; mi++) {
            uint32_t row = (uint32_t)(warp_m * 32 + mi * 16 + (lane & 15));
            uint32_t kb  = (uint32_t)(ks * 32 + (lane >> 4) * 16);
            aoffM[ks][mi] = swz64(row * 64u + kb);
        }
        #pragma unroll
        for (int np = 0; np < 2; np++) {
            uint32_t n  = (uint32_t)(warp_n * 32 + np * 16 + ((lane >> 4) & 1) * 8 + (lane & 7));
            uint32_t kb = (uint32_t)(ks * 32 + ((lane >> 3) & 1) * 16);
            boffM[ks][np] = swz64(n * 64u + kb);
        }
    }
    #pragma unroll
    for (int h = 0; h < 2; h++) {
        #pragma unroll
        for (int mi = 0; mi < 2; mi++) {
            uint32_t row = (uint32_t)(warp_m * 32 + mi * 16 + (lane & 15));
            uint32_t kb  = (uint32_t)(h * 32 + (lane >> 4) * 16);
            aoff8[h][mi] = swz64(row * 64u + kb);
        }
        #pragma unroll
        for (int np = 0; np < 2; np++) {
            uint32_t n  = (uint32_t)(warp_n * 32 + np * 16 + ((lane >> 4) & 1) * 8 + (lane & 7));
            uint32_t kb = (uint32_t)(h * 32 + ((lane >> 3) & 1) * 16);
            boff8[h][np] = swz64(n * 64u + kb);
        }
    }

    float acc[2][4][4];    // main (bf16)
    float acc8[2][4][4];   // correction (fp8, scaled by 512)
    #pragma unroll
    for (int mi = 0; mi < 2; mi++)
        #pragma unroll
        for (int ni = 0; ni < 4; ni++)
            #pragma unroll
            for (int j = 0; j < 4; j++) { acc[mi][ni][j] = 0.0f; acc8[mi][ni][j] = 0.0f; }

    // prologue: fill stages 0..2
    #pragma unroll
    for (int p = 0; p < 3; p++) {
        const int k0 = p * KSTAGE;
        cp_bf16_tile(base + SM_AH(p), Ah + k0, tid);
        cp_bf16_tile(base + SM_BH(p), Bh + k0, tid);
        cp_fp8_tile (base + SM_A8(p), Ah8 + k0, Al8 + k0, tid);
        cp_fp8_tile (base + SM_B8(p), Bh8 + k0, Bl8 + k0, tid);
        asm volatile("cp.async.commit_group;" ::: "memory");
    }

    #pragma unroll 1
    for (int s = 0; s < NSTAGES; s++) {
        const int b = s & 3;
        asm volatile("cp.async.wait_group 2;" ::: "memory");
        __syncthreads();

        if (s + 3 < NSTAGES) {
            const int k0 = (s + 3) * KSTAGE;
            const int nb = (s + 3) & 3;
            cp_bf16_tile(base + SM_AH(nb), Ah + k0, tid);
            cp_bf16_tile(base + SM_BH(nb), Bh + k0, tid);
            cp_fp8_tile (base + SM_A8(nb), Ah8 + k0, Al8 + k0, tid);
            cp_fp8_tile (base + SM_B8(nb), Bh8 + k0, Bl8 + k0, tid);
        }
        asm volatile("cp.async.commit_group;" ::: "memory");

        const uint32_t bAh = base + SM_AH(b);
        const uint32_t bBh = base + SM_BH(b);
        const uint32_t bA8 = base + SM_A8(b);
        const uint32_t bB8 = base + SM_B8(b);

        // ---- main bf16: Ah * Bh ----
        #pragma unroll
        for (int ks = 0; ks < 2; ks++) {
            uint32_t af[2][4], bf[2][4];
            #pragma unroll
            for (int mi = 0; mi < 2; mi++) ldmatrix_x4(af[mi], bAh + aoffM[ks][mi]);
            #pragma unroll
            for (int np = 0; np < 2; np++) ldmatrix_x4(bf[np], bBh + boffM[ks][np]);
            #pragma unroll
            for (int mi = 0; mi < 2; mi++)
                #pragma unroll
                for (int ni = 0; ni < 4; ni++)
                    mma16816(acc[mi][ni], af[mi],
                             bf[ni >> 1][(ni & 1) * 2], bf[ni >> 1][(ni & 1) * 2 + 1]);
        }
        // ---- corr GEMM1: ah8 * bl8 (k=32) ----
        {
            uint32_t a8[2][4], b8[2][4];
            #pragma unroll
            for (int mi = 0; mi < 2; mi++) ldmatrix_x4(a8[mi], bA8 + aoff8[0][mi]);
            #pragma unroll
            for (int np = 0; np < 2; np++) ldmatrix_x4(b8[np], bB8 + boff8[1][np]);
            #pragma unroll
            for (int mi = 0; mi < 2; mi++)
                #pragma unroll
                for (int ni = 0; ni < 4; ni++)
                    mma_fp8(acc8[mi][ni], a8[mi],
                            b8[ni >> 1][(ni & 1) * 2], b8[ni >> 1][(ni & 1) * 2 + 1]);
        }
        // ---- corr GEMM2: al8 * bh8 (k=32) ----
        {
            uint32_t a8[2][4], b8[2][4];
            #pragma unroll
            for (int mi = 0; mi < 2; mi++) ldmatrix_x4(a8[mi], bA8 + aoff8[1][mi]);
            #pragma unroll
            for (int np = 0; np < 2; np++) ldmatrix_x4(b8[np], bB8 + boff8[0][np]);
            #pragma unroll
            for (int mi = 0; mi < 2; mi++)
                #pragma unroll
                for (int ni = 0; ni < 4; ni++)
                    mma_fp8(acc8[mi][ni], a8[mi],
                            b8[ni >> 1][(ni & 1) * 2], b8[ni >> 1][(ni & 1) * 2 + 1]);
        }
    }

    // ---------------- epilogue: combine + bias + online softmax ----------------
    const int q  = lane >> 2;
    const int tq = lane & 3;

    #pragma unroll
    for (int mi = 0; mi < 2; mi++) {
        #pragma unroll
        for (int half = 0; half < 2; half++) {
            float v[8];
            #pragma unroll
            for (int ni = 0; ni < 4; ni++) {
                int col = warp_n * 32 + ni * 8 + tq * 2;
                v[ni * 2 + 0] = acc[mi][ni][half * 2 + 0]
                              + acc8[mi][ni][half * 2 + 0] * INV512 + bias_sm[col];
                v[ni * 2 + 1] = acc[mi][ni][half * 2 + 1]
                              + acc8[mi][ni][half * 2 + 1] * INV512 + bias_sm[col + 1];
            }
            float M = v[0];
            #pragma unroll
            for (int j = 1; j < 8; j++) M = fmaxf(M, v[j]);
            float S = 0.0f;
            #pragma unroll
            for (int j = 0; j < 8; j++) S += __expf(v[j] - M);
            #pragma unroll
            for (int o = 1; o <= 2; o <<= 1) {
                float oM = __shfl_xor_sync(0xffffffffu, M, o);
                float oS = __shfl_xor_sync(0xffffffffu, S, o);
                float nm = fmaxf(M, oM);
                S = S * __expf(M - nm) + oS * __expf(oM - nm);
                M = nm;
            }
            if (tq == 0) {
                int row = warp_m * 32 + mi * 16 + half * 8 + q;
                redM[warp_n][row] = M;
                redS[warp_n][row] = S;
            }
        }
    }
    __syncthreads();

    if (tid < TILE_M) {
        float M = redM[0][tid], S = redS[0][tid];
        #pragma unroll
        for (int w = 1; w < 4; w++) {
            float oM = redM[w][tid], oS = redS[w][tid];
            float nm = fmaxf(M, oM);
            S = S * __expf(M - nm) + oS * __expf(oM - nm);
            M = nm;
        }
        g_partials[pass][(size_t)blockIdx.y * BT + m0 + tid] = make_float2(M, S);
    }
}

// =================================================================
// Kernel 2: exact fp32 target logits
// =================================================================
__global__ __launch_bounds__(128)
void tgt_logit_kernel(const float* __restrict__ x0, const float* __restrict__ w0,
                      const float* __restrict__ b0,
                      const float* __restrict__ x1, const float* __restrict__ w1,
                      const float* __restrict__ b1, const void* __restrict__ tgt)
{
    const int pass = blockIdx.y;
    const float* X  = pass ? x1 : x0;
    const float* W  = pass ? w1 : w0;
    const float* BV = pass ? b1 : b0;
    const int tok = blockIdx.x;

    const bool is64 = target_is_i64(tgt);
    long long t = load_tgt(tgt, tok, is64);
    int tc = (int)t;
    tc = tc < 0 ? 0 : (tc >= VOCAB ? VOCAB - 1 : tc);

    const float4* xv = (const float4*)(X + (size_t)tok * HDIM);
    const float4* wv = (const float4*)(W + (size_t)tc * HDIM);
    float s = 0.0f;
    for (int c = threadIdx.x; c < HDIM / 4; c += blockDim.x) {
        float4 a = xv[c], b = wv[c];
        s += a.x * b.x + a.y * b.y + a.z * b.z + a.w * b.w;
    }
    #pragma unroll
    for (int o = 16; o; o >>= 1) s += __shfl_xor_sync(0xffffffffu, s, o);
    __shared__ float red[4];
    if ((threadIdx.x & 31) == 0) red[threadIdx.x >> 5] = s;
    __syncthreads();
    if (threadIdx.x == 0)
        g_tgt[pass][tok] = red[0] + red[1] + red[2] + red[3] + BV[tc];
}

// =================================================================
// Kernel 3: combine partials -> per-seq sums
// =================================================================
__global__ __launch_bounds__(256)
void combine_kernel(const void* __restrict__ tgt)
{
    const int b = blockIdx.x;
    const int tid = threadIdx.x;
    const bool is64 = target_is_i64(tgt);
    float accp = 0.0f, accr = 0.0f;

    for (int it = 0; it < TSEQ; it += 256) {
        const int tok = b * TSEQ + it + tid;
        long long t = load_tgt(tgt, tok, is64);
        if (t != IGNORE_INDEX) {
            #pragma unroll
            for (int p = 0; p < 2; p++) {
                float M = -INFINITY, S = 0.0f;
                #pragma unroll 1
                for (int c = 0; c < NTILES_N; c++) {
                    float2 pc = g_partials[p][(size_t)c * BT + tok];
                    float nm = fmaxf(M, pc.x);
                    S = S * __expf(M - nm) + pc.y * __expf(pc.x - nm);
                    M = nm;
                }
                float lp = g_tgt[p][tok] - (M + logf(S));
                if (p == 0) accp += lp; else accr += lp;
            }
        }
    }
    #pragma unroll
    for (int o = 16; o; o >>= 1) {
        accp += __shfl_xor_sync(0xffffffffu, accp, o);
        accr += __shfl_xor_sync(0xffffffffu, accr, o);
    }
    __shared__ float sp[8], sr[8];
    if ((tid & 31) == 0) { sp[tid >> 5] = accp; sr[tid >> 5] = accr; }
    __syncthreads();
    if (tid == 0) {
        float a = 0.0f, r = 0.0f;
        #pragma unroll
        for (int i = 0; i < 8; i++) { a += sp[i]; r += sr[i]; }
        g_seq[0][b] = a;
        g_seq[1][b] = r;
    }
}

// =================================================================
// Kernel 4: final KTO loss
// =================================================================
__global__ void final_kernel(const void* __restrict__ pref,
                             const float* __restrict__ kl,
                             float* __restrict__ out, int out_size)
{
    if (threadIdx.x != 0) return;
    const int* pw = (const int*)pref;
    bool isInt = true;
    int li[BSEQ];
    #pragma unroll
    for (int i = 0; i < BSEQ; i++) {
        int v = pw[i];
        if (v != 0 && v != 1) isInt = false;
        li[i] = v;
    }
    const unsigned char* pb = (const unsigned char*)pref;
    int lab[BSEQ];
    #pragma unroll
    for (int i = 0; i < BSEQ; i++)
        lab[i] = isInt ? li[i] : (pb[i] != 0 ? 1 : 0);

    const float kl0 = kl[0];
    float loss = 0.0f, ch = 0.0f, rj = 0.0f;
    #pragma unroll
    for (int b = 0; b < BSEQ; b++) {
        float lr   = g_seq[0][b] - g_seq[1][b];
        float mult = lab[b] ? 1.0f : -1.0f;
        float z    = BETA * (lr - kl0) * mult;
        loss += 1.0f - 1.0f / (1.0f + expf(-z));
        float rw = BETA * lr;
        if (lab[b]) ch += rw; else rj += rw;
    }
    loss /= (float)BT;
    if (out_size > 0) out[0] = loss;
    if (out_size > 1) out[1] = ch;
    if (out_size > 2) out[2] = rj;
}

// =================================================================
extern "C" void kernel_launch(void* const* d_in, const int* in_sizes, int n_in,
                              void* d_out, int out_size)
{
    const float* x    = (const float*)d_in[0];
    const float* w    = (const float*)d_in[1];
    const void*  tgt  = d_in[2];
    const float* bias = (const float*)d_in[3];
    const void*  pref = d_in[4];
    const float* xr   = (const float*)d_in[5];
    const float* wr   = (const float*)d_in[6];
    const float* br   = (const float*)d_in[7];
    const float* kl   = (const float*)d_in[8];

    __nv_bfloat16 *whi, *xhi;
    unsigned char *wh8, *wl8, *xh8, *xl8;
    cudaGetSymbolAddress((void**)&whi, g_whi);
    cudaGetSymbolAddress((void**)&wh8, g_wh8);
    cudaGetSymbolAddress((void**)&wl8, g_wl8);
    cudaGetSymbolAddress((void**)&xhi, g_xhi);
    cudaGetSymbolAddress((void**)&xh8, g_xh8);
    cudaGetSymbolAddress((void**)&xl8, g_xl8);

    const long long WN4 = (long long)VOCAB * HDIM / 4;
    const long long XN4 = (long long)BT * HDIM / 4;
    const size_t WOFF = (size_t)VOCAB * HDIM;
    const size_t XOFF = (size_t)BT * HDIM;

    // launches 0..3 (ncu -s 5 skips these + tgt, captures lse)
    split3_kernel<<<2048, 256>>>(w,  whi,        wh8,        wl8,        WN4);
    split3_kernel<<<2048, 256>>>(wr, whi + WOFF, wh8 + WOFF, wl8 + WOFF, WN4);
    split3_kernel<<<256, 256>>>(x,  xhi,        xh8,        xl8,        XN4);
    split3_kernel<<<256, 256>>>(xr, xhi + XOFF, xh8 + XOFF, xl8 + XOFF, XN4);

    // launch 4
    tgt_logit_kernel<<<dim3(BT, 2), 128>>>(x, w, bias, xr, wr, br, tgt);

    // launch 5 — the GEMM (ncu target)
    cudaFuncSetAttribute(lse_mma_kernel,
                         cudaFuncAttributeMaxDynamicSharedMemorySize, SMEM_DYN);
    dim3 g1(NTILES_M, NTILES_N, 2);
    lse_mma_kernel<<<g1, NTHREADS, SMEM_DYN>>>(bias, br);

    combine_kernel<<<BSEQ, 256>>>(tgt);
    final_kernel<<<1, 32>>>(pref, kl, (float*)d_out, out_size);
}